// round 2
// baseline (speedup 1.0000x reference)
#include <cuda_runtime.h>

// out[i,j] = x0[i,j] * (x_l[i] . w) + b[j] + x_l[i,j]
// B = 65536 rows, DIM = 1024.
// One WARP per row: 32 lanes x 8 float4 = 1024 floats. In-warp shuffle
// reduction only -- no shared memory, no __syncthreads.

#define DIM 1024
#define ROW_F4 (DIM / 4)        // 256 float4 per row
#define WARPS_PER_BLOCK 8
#define THREADS (WARPS_PER_BLOCK * 32)
#define F4_PER_LANE 8           // 256 / 32

__global__ __launch_bounds__(THREADS) void dcn_kernel(
    const float* __restrict__ x_l,
    const float* __restrict__ x_0,
    const float* __restrict__ w,
    const float* __restrict__ b,
    float* __restrict__ out)
{
    const int warp = blockIdx.x * WARPS_PER_BLOCK + (threadIdx.x >> 5); // row id
    const int lane = threadIdx.x & 31;
    const size_t base4 = (size_t)warp * ROW_F4;

    const float4* __restrict__ xl4 = reinterpret_cast<const float4*>(x_l);
    const float4* __restrict__ x04 = reinterpret_cast<const float4*>(x_0);
    const float4* __restrict__ w4  = reinterpret_cast<const float4*>(w);
    const float4* __restrict__ b4  = reinterpret_cast<const float4*>(b);
    float4* __restrict__ out4      = reinterpret_cast<float4*>(out);

    // Front-batched x_l loads (held in registers for the epilogue) + w (L1/L2 hit).
    float4 a[F4_PER_LANE];
    float local = 0.0f;
    #pragma unroll
    for (int k = 0; k < F4_PER_LANE; k++)
        a[k] = xl4[base4 + k * 32 + lane];
    #pragma unroll
    for (int k = 0; k < F4_PER_LANE; k++) {
        float4 wv = w4[k * 32 + lane];
        local += a[k].x * wv.x + a[k].y * wv.y + a[k].z * wv.z + a[k].w * wv.w;
    }

    // In-warp butterfly reduction: every lane ends with the full row dot.
    #pragma unroll
    for (int off = 16; off > 0; off >>= 1)
        local += __shfl_xor_sync(0xffffffffu, local, off);
    const float s = local;

    // Epilogue: out = x0 * s + (b + x_l). Compiler batches the x_0 loads.
    #pragma unroll
    for (int k = 0; k < F4_PER_LANE; k++) {
        float4 c  = x04[base4 + k * 32 + lane];
        float4 bv = b4[k * 32 + lane];
        float4 o;
        o.x = fmaf(c.x, s, bv.x + a[k].x);
        o.y = fmaf(c.y, s, bv.y + a[k].y);
        o.z = fmaf(c.z, s, bv.z + a[k].z);
        o.w = fmaf(c.w, s, bv.w + a[k].w);
        out4[base4 + k * 32 + lane] = o;
    }
}

extern "C" void kernel_launch(void* const* d_in, const int* in_sizes, int n_in,
                              void* d_out, int out_size)
{
    const float* x_l = (const float*)d_in[0];
    const float* x_0 = (const float*)d_in[1];
    const float* w   = (const float*)d_in[2];
    const float* b   = (const float*)d_in[3];
    float* out       = (float*)d_out;

    const int B = in_sizes[0] / DIM;              // 65536 rows
    const int grid = B / WARPS_PER_BLOCK;         // 8192 blocks
    dcn_kernel<<<grid, THREADS>>>(x_l, x_0, w, b, out);
}

// round 3
// speedup vs baseline: 1.1071x; 1.1071x over previous
#include <cuda_runtime.h>

// out[i,j] = x0[i,j] * (x_l[i] . w) + b[j] + x_l[i,j]
// B = 65536 rows, DIM = 1024.
// One block per row, 256 threads, float4 per thread.
// All global loads issued BEFORE the reduction barrier so the x_0 stream
// latency overlaps the dot-product reduction. Streaming cache hints on the
// three 256 MB streams; w/b stay L2/L1 resident.

#define DIM 1024
#define THREADS 256  // DIM/4

__global__ __launch_bounds__(THREADS) void dcn_kernel(
    const float* __restrict__ x_l,
    const float* __restrict__ x_0,
    const float* __restrict__ w,
    const float* __restrict__ b,
    float* __restrict__ out)
{
    const int row = blockIdx.x;
    const int t   = threadIdx.x;
    const size_t base4 = (size_t)row * (DIM / 4);

    const float4* __restrict__ xl4 = reinterpret_cast<const float4*>(x_l);
    const float4* __restrict__ x04 = reinterpret_cast<const float4*>(x_0);
    const float4* __restrict__ w4  = reinterpret_cast<const float4*>(w);
    const float4* __restrict__ b4  = reinterpret_cast<const float4*>(b);
    float4* __restrict__ out4      = reinterpret_cast<float4*>(out);

    // Front-batch ALL global loads: both streams + the L2-resident vectors.
    float4 a  = __ldcs(&xl4[base4 + t]);   // x_l stream (read once)
    float4 c  = __ldcs(&x04[base4 + t]);   // x_0 stream (read once)
    float4 wv = __ldg(&w4[t]);             // 4 KB, L2/L1 resident
    float4 bv = __ldg(&b4[t]);             // 4 KB, L2/L1 resident

    // Partial dot product.
    float local = a.x * wv.x + a.y * wv.y + a.z * wv.z + a.w * wv.w;

    // Warp butterfly reduce.
    #pragma unroll
    for (int off = 16; off > 0; off >>= 1)
        local += __shfl_xor_sync(0xffffffffu, local, off);

    __shared__ float warpsum[THREADS / 32];
    if ((t & 31) == 0) warpsum[t >> 5] = local;
    __syncthreads();

    float s = 0.0f;
    #pragma unroll
    for (int i = 0; i < THREADS / 32; i++) s += warpsum[i];

    // Pure-ALU epilogue: everything already in registers.
    float4 o;
    o.x = fmaf(c.x, s, bv.x + a.x);
    o.y = fmaf(c.y, s, bv.y + a.y);
    o.z = fmaf(c.z, s, bv.z + a.z);
    o.w = fmaf(c.w, s, bv.w + a.w);
    __stcs(&out4[base4 + t], o);           // streaming store (write once)
}

extern "C" void kernel_launch(void* const* d_in, const int* in_sizes, int n_in,
                              void* d_out, int out_size)
{
    const float* x_l = (const float*)d_in[0];
    const float* x_0 = (const float*)d_in[1];
    const float* w   = (const float*)d_in[2];
    const float* b   = (const float*)d_in[3];
    float* out       = (float*)d_out;

    const int B = in_sizes[0] / DIM;  // 65536
    dcn_kernel<<<B, THREADS>>>(x_l, x_0, w, b, out);
}